// round 14
// baseline (speedup 1.0000x reference)
#include <cuda_runtime.h>

#define BB 2
#define NN 512
#define DM 256
#define HH 8
#define HD 32
#define HF 16
#define TQ 4          // query rows per block
#define MT 64         // key rows per tile
#define NT (NN/MT)    // 8 tiles
#define KP 260        // sK row pitch
#define XP 28         // sXm row pitch: 24 x + nh + ne + pad
#define SCALE 0.17677669529663687f
#define LOG2E 1.4426950408889634f

__device__ float g_Q[BB*NN*DM];
__device__ float g_K[BB*NN*DM];
__device__ float g_V[BB*NN*DM];
__device__ float g_ctx[BB*NN*DM];

__constant__ float cFREQ[HF] = {
    1.0f, 0.5623413251903491f, 0.31622776601683794f, 0.17782794100389228f,
    0.1f, 0.05623413251903491f, 0.031622776601683794f, 0.017782794100389228f,
    0.01f, 0.005623413251903491f, 0.0031622776601683794f, 0.0017782794100389228f,
    0.001f, 0.0005623413251903491f, 0.00031622776601683794f, 0.00017782794100389228f };

__device__ __forceinline__ float ex2(float x) {
    float r; asm("ex2.approx.ftz.f32 %0, %1;" : "=f"(r) : "f"(x)); return r;
}

// ---- cp.async helpers -------------------------------------------------------
__device__ __forceinline__ void cpa16(void* smem_ptr, const void* gptr) {
    unsigned sa = (unsigned)__cvta_generic_to_shared(smem_ptr);
    asm volatile("cp.async.cg.shared.global [%0], [%1], 16;\n" :: "r"(sa), "l"(gptr) : "memory");
}
__device__ __forceinline__ void cpa_commit() {
    asm volatile("cp.async.commit_group;\n" ::: "memory");
}
__device__ __forceinline__ void cpa_wait0() {
    asm volatile("cp.async.wait_group 0;\n" ::: "memory");
}

// ---------------------------------------------------------------------------
// k-major staged GEMM, double-buffered smem. [R6-verified]
// block = 128 threads, tile 32 rows x 64 cols, thread tile 4x4.
// ---------------------------------------------------------------------------
__device__ __forceinline__ void gemm32(const float* __restrict__ A,
                                       const float* __restrict__ W,
                                       const float* __restrict__ bias,
                                       float* __restrict__ O)
{
    __shared__ __align__(16) float sA[2][16][36];
    __shared__ __align__(16) float sW[2][16][68];
    const int tid = threadIdx.x;
    const int r0 = blockIdx.x * 32, c0 = blockIdx.y * 64;
    const int ty = tid >> 4, tx = tid & 15;

    float acc[4][4];
#pragma unroll
    for (int i = 0; i < 4; ++i)
#pragma unroll
        for (int j = 0; j < 4; ++j) acc[i][j] = 0.f;

    const int arow = tid >> 2, ako = (tid & 3) << 2;
    const int wrow = tid >> 1, wko = (tid & 1) << 3;

    const float* ap = A + (r0 + arow) * DM + ako;
    const float* wp = W + (c0 + wrow) * DM + wko;

    {
        float4 pa  = *(const float4*)(ap);
        float4 pw0 = *(const float4*)(wp);
        float4 pw1 = *(const float4*)(wp + 4);
        sA[0][ako+0][arow] = pa.x; sA[0][ako+1][arow] = pa.y;
        sA[0][ako+2][arow] = pa.z; sA[0][ako+3][arow] = pa.w;
        sW[0][wko+0][wrow] = pw0.x; sW[0][wko+1][wrow] = pw0.y;
        sW[0][wko+2][wrow] = pw0.z; sW[0][wko+3][wrow] = pw0.w;
        sW[0][wko+4][wrow] = pw1.x; sW[0][wko+5][wrow] = pw1.y;
        sW[0][wko+6][wrow] = pw1.z; sW[0][wko+7][wrow] = pw1.w;
    }
    __syncthreads();

    int buf = 0;
    for (int k0 = 0; k0 < DM; k0 += 16, buf ^= 1) {
        const bool has_next = (k0 + 16 < DM);
        float4 pa, pw0, pw1;
        if (has_next) {
            pa  = *(const float4*)(ap + k0 + 16);
            pw0 = *(const float4*)(wp + k0 + 16);
            pw1 = *(const float4*)(wp + k0 + 20);
        }
#pragma unroll
        for (int k = 0; k < 16; ++k) {
            float4 av = *(const float4*)&sA[buf][k][ty*4];
            float4 wv = *(const float4*)&sW[buf][k][tx*4];
            acc[0][0] = fmaf(av.x, wv.x, acc[0][0]);
            acc[0][1] = fmaf(av.x, wv.y, acc[0][1]);
            acc[0][2] = fmaf(av.x, wv.z, acc[0][2]);
            acc[0][3] = fmaf(av.x, wv.w, acc[0][3]);
            acc[1][0] = fmaf(av.y, wv.x, acc[1][0]);
            acc[1][1] = fmaf(av.y, wv.y, acc[1][1]);
            acc[1][2] = fmaf(av.y, wv.z, acc[1][2]);
            acc[1][3] = fmaf(av.y, wv.w, acc[1][3]);
            acc[2][0] = fmaf(av.z, wv.x, acc[2][0]);
            acc[2][1] = fmaf(av.z, wv.y, acc[2][1]);
            acc[2][2] = fmaf(av.z, wv.z, acc[2][2]);
            acc[2][3] = fmaf(av.z, wv.w, acc[2][3]);
            acc[3][0] = fmaf(av.w, wv.x, acc[3][0]);
            acc[3][1] = fmaf(av.w, wv.y, acc[3][1]);
            acc[3][2] = fmaf(av.w, wv.z, acc[3][2]);
            acc[3][3] = fmaf(av.w, wv.w, acc[3][3]);
        }
        if (has_next) {
            int nb = buf ^ 1;
            sA[nb][ako+0][arow] = pa.x; sA[nb][ako+1][arow] = pa.y;
            sA[nb][ako+2][arow] = pa.z; sA[nb][ako+3][arow] = pa.w;
            sW[nb][wko+0][wrow] = pw0.x; sW[nb][wko+1][wrow] = pw0.y;
            sW[nb][wko+2][wrow] = pw0.z; sW[nb][wko+3][wrow] = pw0.w;
            sW[nb][wko+4][wrow] = pw1.x; sW[nb][wko+5][wrow] = pw1.y;
            sW[nb][wko+6][wrow] = pw1.z; sW[nb][wko+7][wrow] = pw1.w;
        }
        __syncthreads();
    }
    float4 bv = *(const float4*)(bias + c0 + tx*4);
#pragma unroll
    for (int i = 0; i < 4; ++i) {
        float4 o = make_float4(acc[i][0]+bv.x, acc[i][1]+bv.y,
                               acc[i][2]+bv.z, acc[i][3]+bv.w);
        *(float4*)(O + (r0 + ty*4 + i) * DM + c0 + tx*4) = o;
    }
}

// ---------------------------------------------------------------------------
// k-major staged GEMM, tile 16 rows x 64 cols, 128 threads, thread tile 2x4.
// Doubles the grid for the under-filled output projection.
// ---------------------------------------------------------------------------
__device__ __forceinline__ void gemm16(const float* __restrict__ A,
                                       const float* __restrict__ W,
                                       const float* __restrict__ bias,
                                       float* __restrict__ O)
{
    __shared__ __align__(16) float sA[2][16][20];   // [buf][k][row 16]
    __shared__ __align__(16) float sW[2][16][68];
    const int tid = threadIdx.x;
    const int r0 = blockIdx.x * 16, c0 = blockIdx.y * 64;
    const int ty = tid >> 4, tx = tid & 15;         // 8 x 16

    float acc[2][4];
#pragma unroll
    for (int i = 0; i < 2; ++i)
#pragma unroll
        for (int j = 0; j < 4; ++j) acc[i][j] = 0.f;

    const int arow = tid >> 2, ako = (tid & 3) << 2;   // threads < 64
    const int wrow = tid >> 1, wko = (tid & 1) << 3;

    const float* ap = A + (r0 + (arow & 15)) * DM + ako;
    const float* wp = W + (c0 + wrow) * DM + wko;

    {
        if (tid < 64) {
            float4 pa = *(const float4*)(ap);
            sA[0][ako+0][arow] = pa.x; sA[0][ako+1][arow] = pa.y;
            sA[0][ako+2][arow] = pa.z; sA[0][ako+3][arow] = pa.w;
        }
        float4 pw0 = *(const float4*)(wp);
        float4 pw1 = *(const float4*)(wp + 4);
        sW[0][wko+0][wrow] = pw0.x; sW[0][wko+1][wrow] = pw0.y;
        sW[0][wko+2][wrow] = pw0.z; sW[0][wko+3][wrow] = pw0.w;
        sW[0][wko+4][wrow] = pw1.x; sW[0][wko+5][wrow] = pw1.y;
        sW[0][wko+6][wrow] = pw1.z; sW[0][wko+7][wrow] = pw1.w;
    }
    __syncthreads();

    int buf = 0;
    for (int k0 = 0; k0 < DM; k0 += 16, buf ^= 1) {
        const bool has_next = (k0 + 16 < DM);
        float4 pa, pw0, pw1;
        if (has_next) {
            if (tid < 64) pa = *(const float4*)(ap + k0 + 16);
            pw0 = *(const float4*)(wp + k0 + 16);
            pw1 = *(const float4*)(wp + k0 + 20);
        }
#pragma unroll
        for (int k = 0; k < 16; ++k) {
            float2 av = *(const float2*)&sA[buf][k][ty*2];
            float4 wv = *(const float4*)&sW[buf][k][tx*4];
            acc[0][0] = fmaf(av.x, wv.x, acc[0][0]);
            acc[0][1] = fmaf(av.x, wv.y, acc[0][1]);
            acc[0][2] = fmaf(av.x, wv.z, acc[0][2]);
            acc[0][3] = fmaf(av.x, wv.w, acc[0][3]);
            acc[1][0] = fmaf(av.y, wv.x, acc[1][0]);
            acc[1][1] = fmaf(av.y, wv.y, acc[1][1]);
            acc[1][2] = fmaf(av.y, wv.z, acc[1][2]);
            acc[1][3] = fmaf(av.y, wv.w, acc[1][3]);
        }
        if (has_next) {
            int nb = buf ^ 1;
            if (tid < 64) {
                sA[nb][ako+0][arow] = pa.x; sA[nb][ako+1][arow] = pa.y;
                sA[nb][ako+2][arow] = pa.z; sA[nb][ako+3][arow] = pa.w;
            }
            sW[nb][wko+0][wrow] = pw0.x; sW[nb][wko+1][wrow] = pw0.y;
            sW[nb][wko+2][wrow] = pw0.z; sW[nb][wko+3][wrow] = pw0.w;
            sW[nb][wko+4][wrow] = pw1.x; sW[nb][wko+5][wrow] = pw1.y;
            sW[nb][wko+6][wrow] = pw1.z; sW[nb][wko+7][wrow] = pw1.w;
        }
        __syncthreads();
    }
    float4 bv = *(const float4*)(bias + c0 + tx*4);
#pragma unroll
    for (int i = 0; i < 2; ++i) {
        float4 o = make_float4(acc[i][0]+bv.x, acc[i][1]+bv.y,
                               acc[i][2]+bv.z, acc[i][3]+bv.w);
        *(float4*)(O + (r0 + ty*2 + i) * DM + c0 + tx*4) = o;
    }
}

__global__ void __launch_bounds__(128) k_qkv(const float* __restrict__ h,
                                             const float* __restrict__ Wq,
                                             const float* __restrict__ Wk,
                                             const float* __restrict__ Wv,
                                             const float* __restrict__ bq,
                                             const float* __restrict__ bk,
                                             const float* __restrict__ bv)
{
    const int z = blockIdx.z;
    const float* W = (z == 0) ? Wq : (z == 1) ? Wk : Wv;
    const float* b = (z == 0) ? bq : (z == 1) ? bk : bv;
    float* O = (z == 0) ? g_Q : (z == 1) ? g_K : g_V;
    gemm32(h, W, b, O);
}

__global__ void __launch_bounds__(128) k_out(const float* __restrict__ Wo,
                                             const float* __restrict__ bo,
                                             float* __restrict__ out)
{
    gemm16(g_ctx, Wo, bo, out);
}

// ---------------------------------------------------------------------------
// Fused attention (R13) + norm-precompute geometry:
// staging stores per-m [x(24), nh, ne]; phase A uses dh2 = nqh+nm-2*dot.
// grid: (NN/TQ, BB) = (128, 2), block: 256 threads
// ---------------------------------------------------------------------------
__global__ void __launch_bounds__(256, 2) k_attn(const float* __restrict__ X,
                                                 const float* __restrict__ EB,
                                                 const float* __restrict__ WKER,
                                                 const float* __restrict__ BETA)
{
    extern __shared__ __align__(16) float smem[];
    float* sK    = smem;                 // 64*260
    float* sQ    = sK + MT*KP;           // 4*256
    float* sS    = sQ + TQ*DM;           // 4*8*64
    float* sXm   = sS + TQ*HH*MT;        // 64*28
    float* sCoef = sXm + MT*XP;          // 8*4

    const int b   = blockIdx.y;
    const int n0  = blockIdx.x * TQ;
    const int tid = threadIdx.x;

    const int qA = tid >> 6, mlA = tid & 63;   // phase A identity
    const int hB = tid >> 5, dB  = tid & 31;   // phase B identity

    const float* kgb = g_K + b*NN*DM;
    const float* xgb = X + b*NN*24;

    int krow[16], kcol[16];
#pragma unroll
    for (int i = 0; i < 16; ++i) { int idx = tid + 256*i; krow[i] = idx >> 6; kcol[i] = idx & 63; }

    // ---- block setup ----
    {
        int q = tid >> 6, i = tid & 63;
        ((float4*)sQ)[tid] = ((const float4*)(g_Q + (b*NN + n0 + q)*DM))[i];
    }
    if (tid < HH*3) {
        int hh = tid/3, c = tid%3;
        float w = WKER[hh*3+c] * BETA[hh] * LOG2E;   // fold log2e
        sCoef[hh*4+c] = (c == 1) ? w : -w;           // [-dh, +sdot, -de2]
    }
    // stage X tile 0: one row per thread (tid<64), with norms
    if (tid < MT) {
        const float4* xr = (const float4*)(xgb + tid*24);   // 96B-aligned
        float4 v0 = xr[0], v1 = xr[1], v2 = xr[2], v3 = xr[3], v4 = xr[4], v5 = xr[5];
        float* d = &sXm[tid*XP];
        ((float4*)d)[0] = v0; ((float4*)d)[1] = v1; ((float4*)d)[2] = v2;
        ((float4*)d)[3] = v3; ((float4*)d)[4] = v4; ((float4*)d)[5] = v5;
        float nh = v0.x*v0.x + v0.y*v0.y + v0.z*v0.z + v0.w*v0.w
                 + v1.x*v1.x + v1.y*v1.y + v1.z*v1.z + v1.w*v1.w;
        float ne = v4.x*v4.x + v4.y*v4.y + v4.z*v4.z + v4.w*v4.w
                 + v5.x*v5.x + v5.y*v5.y + v5.z*v5.z + v5.w*v5.w;
        d[24] = nh; d[25] = ne;
    }
    // stage K tile 0 via cp.async
    {
        const float* kg = kgb;
#pragma unroll
        for (int i = 0; i < 16; ++i)
            cpa16(&sK[krow[i]*KP + kcol[i]*4], kg + krow[i]*DM + kcol[i]*4);
        cpa_commit();
    }

    float xq[24];
    {
        const float* xp = X + (b*NN + n0 + qA)*24;
#pragma unroll
        for (int j = 0; j < 24; ++j) xq[j] = xp[j];
    }
    float nqh = 0.f, nqe = 0.f;
#pragma unroll
    for (int j = 0; j < 8; ++j) nqh = fmaf(xq[j], xq[j], nqh);
#pragma unroll
    for (int j = 0; j < 8; ++j) nqe = fmaf(xq[16+j], xq[16+j], nqe);
    const float oneq = 1.0f - nqh;

    float Ssum[TQ], acc[TQ];
#pragma unroll
    for (int q = 0; q < TQ; ++q) { Ssum[q] = 0.f; acc[q] = 0.f; }

    cpa_wait0();
    __syncthreads();

    for (int t = 0; t < NT; ++t) {
        // ---- Phase A: geometry (norm trick) + RoPE scores -> p = 2^sc ----
        {
            const float* xm = &sXm[mlA*XP];
            float dth = 0.f, sd = 0.f, dte = 0.f;
#pragma unroll
            for (int j = 0; j < 8; ++j) dth = fmaf(xq[j],    xm[j],    dth);
#pragma unroll
            for (int j = 0; j < 8; ++j) sd  = fmaf(xq[8+j],  xm[8+j],  sd);
#pragma unroll
            for (int j = 0; j < 8; ++j) dte = fmaf(xq[16+j], xm[16+j], dte);
            const float nm = xm[24], nem = xm[25];
            float dh2 = fmaf(-2.f, dth, nqh + nm);
            float de2 = fmaxf(fmaf(-2.f, dte, nqe + nem), 0.f);
            const float om = 1.0f - nm;

            float tt = fmaxf(2.0f * dh2 / (oneq * om), 1e-6f);
            float dh = __logf(1.0f + tt + sqrtf(tt * (tt + 2.0f)));
            float sdc = fminf(fmaxf(sd, -1.0f + 1e-6f), 1.0f - 1e-6f);
            float ds = acosf(sdc);
            float dist = sqrtf(fmaf(dh, dh, fmaf(ds, ds, de2)));

            float cs[HF], sn[HF];
#pragma unroll
            for (int f = 0; f < HF; ++f) __sincosf(dist * cFREQ[f], &sn[f], &cs[f]);

            const float ebl = EB[(b*NN + n0 + qA)*NN + t*MT + mlA] * LOG2E;
            const float* krowp = &sK[mlA*KP];

#pragma unroll
            for (int hh = 0; hh < HH; ++hh) {
                const float4* kq = (const float4*)(krowp + hh*HD);
                const float4* qq = (const float4*)(sQ + qA*DM + hh*HD);
                float sa = 0.f, sb = 0.f;
#pragma unroll
                for (int f4 = 0; f4 < 8; ++f4) {
                    float4 kv = kq[f4];
                    float4 qv = qq[f4];
                    const int f0 = f4*2;
                    float same0 = fmaf(qv.x, kv.x, qv.y*kv.y);
                    float crs0  = fmaf(qv.x, kv.y, -qv.y*kv.x);
                    sa = fmaf(cs[f0], same0, sa);
                    sb = fmaf(sn[f0], crs0,  sb);
                    float same1 = fmaf(qv.z, kv.z, qv.w*kv.w);
                    float crs1  = fmaf(qv.z, kv.w, -qv.w*kv.z);
                    sa = fmaf(cs[f0+1], same1, sa);
                    sb = fmaf(sn[f0+1], crs1,  sb);
                }
                float sc = fmaf(sa + sb, SCALE * LOG2E, ebl);
                sc = fmaf(sCoef[hh*4+0], dh,  sc);
                sc = fmaf(sCoef[hh*4+1], sd,  sc);
                sc = fmaf(sCoef[hh*4+2], de2, sc);
                sS[(qA*HH + hh)*MT + mlA] = ex2(sc);
            }
        }
        __syncthreads();   // sS(p) ready; sK/sXm free for restage

        // ---- restage next tile (overlaps phase B) ----
        if (t + 1 < NT) {
            const float* kg = kgb + (t+1)*MT*DM;
#pragma unroll
            for (int i = 0; i < 16; ++i)
                cpa16(&sK[krow[i]*KP + kcol[i]*4], kg + krow[i]*DM + kcol[i]*4);
            cpa_commit();
            if (tid < MT) {
                const float4* xr = (const float4*)(xgb + (t+1)*MT*24 + tid*24);
                float4 v0 = xr[0], v1 = xr[1], v2 = xr[2], v3 = xr[3], v4 = xr[4], v5 = xr[5];
                float* d = &sXm[tid*XP];
                ((float4*)d)[0] = v0; ((float4*)d)[1] = v1; ((float4*)d)[2] = v2;
                ((float4*)d)[3] = v3; ((float4*)d)[4] = v4; ((float4*)d)[5] = v5;
                float nh = v0.x*v0.x + v0.y*v0.y + v0.z*v0.z + v0.w*v0.w
                         + v1.x*v1.x + v1.y*v1.y + v1.z*v1.z + v1.w*v1.w;
                float ne = v4.x*v4.x + v4.y*v4.y + v4.z*v4.z + v4.w*v4.w
                         + v5.x*v5.x + v5.y*v5.y + v5.z*v5.z + v5.w*v5.w;
                d[24] = nh; d[25] = ne;
            }
        }

        // ---- Phase B: normalizer sum (read-only) + PV ----
        {
#pragma unroll
            for (int q = 0; q < TQ; ++q) {
                const float* srow = &sS[(q*HH + hB)*MT];
                Ssum[q] += srow[dB] + srow[dB + 32];
            }
            const float* vb = g_V + (b*NN + t*MT)*DM + hB*HD + dB;
#pragma unroll 4
            for (int m4 = 0; m4 < MT/4; ++m4) {
                float v0 = vb[(m4*4+0)*DM];
                float v1 = vb[(m4*4+1)*DM];
                float v2 = vb[(m4*4+2)*DM];
                float v3 = vb[(m4*4+3)*DM];
#pragma unroll
                for (int q = 0; q < TQ; ++q) {
                    float4 p = *(const float4*)&sS[(q*HH + hB)*MT + m4*4];
                    acc[q] = fmaf(p.x, v0, fmaf(p.y, v1, fmaf(p.z, v2, fmaf(p.w, v3, acc[q]))));
                }
            }
        }
        cpa_wait0();
        __syncthreads();
    }

    // ---- final: reduce normalizer once, write out ----
#pragma unroll
    for (int q = 0; q < TQ; ++q) {
        float s = Ssum[q];
#pragma unroll
        for (int o = 16; o; o >>= 1) s += __shfl_xor_sync(0xffffffffu, s, o);
        g_ctx[(b*NN + n0 + q)*DM + tid] = acc[q] / s;
    }
}

// ---------------------------------------------------------------------------
extern "C" void kernel_launch(void* const* d_in, const int* in_sizes, int n_in,
                              void* d_out, int out_size)
{
    (void)in_sizes; (void)n_in; (void)out_size;
    const float* h    = (const float*)d_in[0];
    const float* x    = (const float*)d_in[1];
    const float* Wq   = (const float*)d_in[2];
    const float* bq   = (const float*)d_in[3];
    const float* Wk   = (const float*)d_in[4];
    const float* bk   = (const float*)d_in[5];
    const float* Wv   = (const float*)d_in[6];
    const float* bv   = (const float*)d_in[7];
    const float* Wo   = (const float*)d_in[8];
    const float* bo   = (const float*)d_in[9];
    const float* wker = (const float*)d_in[10];
    const float* beta = (const float*)d_in[11];
    const float* eb   = (const float*)d_in[12];
    float* out = (float*)d_out;

    const int smem_attn = (MT*KP + TQ*DM + TQ*HH*MT + MT*XP + HH*4) * (int)sizeof(float);
    static int attr_set = 0;
    if (!attr_set) {
        cudaFuncSetAttribute(k_attn, cudaFuncAttributeMaxDynamicSharedMemorySize, smem_attn);
        attr_set = 1;
    }

    k_qkv<<<dim3((BB*NN)/32, DM/64, 3), 128>>>(h, Wq, Wk, Wv, bq, bk, bv);
    k_attn<<<dim3(NN/TQ, BB), 256, smem_attn>>>(x, eb, wker, beta);
    k_out<<<dim3((BB*NN)/16, DM/64), 128>>>(Wo, bo, out);
}

// round 15
// speedup vs baseline: 1.0667x; 1.0667x over previous
#include <cuda_runtime.h>

#define BB 2
#define NN 512
#define DM 256
#define HH 8
#define HD 32
#define HF 16
#define TQ 8          // query rows per block
#define MT 32         // key rows per tile
#define MSPL 4        // m-split
#define MR (NN/MSPL)  // 128 m rows per block
#define NT (MR/MT)    // 4 tiles
#define KP 260        // sK row pitch
#define XP 25         // sXm row pitch (odd -> conflict-free)
#define SCALE 0.17677669529663687f
#define LOG2E 1.4426950408889634f

__device__ float g_Q[BB*NN*DM];
__device__ float g_K[BB*NN*DM];
__device__ float g_V[BB*NN*DM];
__device__ float g_accP[MSPL*BB*NN*DM];
__device__ float g_SP[MSPL*BB*NN*HH];

__constant__ float cFREQ[HF] = {
    1.0f, 0.5623413251903491f, 0.31622776601683794f, 0.17782794100389228f,
    0.1f, 0.05623413251903491f, 0.031622776601683794f, 0.017782794100389228f,
    0.01f, 0.005623413251903491f, 0.0031622776601683794f, 0.0017782794100389228f,
    0.001f, 0.0005623413251903491f, 0.00031622776601683794f, 0.00017782794100389228f };

__device__ __forceinline__ float ex2(float x) {
    float r; asm("ex2.approx.ftz.f32 %0, %1;" : "=f"(r) : "f"(x)); return r;
}

// ---- cp.async helpers -------------------------------------------------------
__device__ __forceinline__ void cpa16(void* smem_ptr, const void* gptr) {
    unsigned sa = (unsigned)__cvta_generic_to_shared(smem_ptr);
    asm volatile("cp.async.cg.shared.global [%0], [%1], 16;\n" :: "r"(sa), "l"(gptr) : "memory");
}
__device__ __forceinline__ void cpa_commit() {
    asm volatile("cp.async.commit_group;\n" ::: "memory");
}
__device__ __forceinline__ void cpa_wait0() {
    asm volatile("cp.async.wait_group 0;\n" ::: "memory");
}

// ---------------------------------------------------------------------------
// k-major staged GEMM, double-buffered smem. [R6-verified]
// MERGE=0: plain A rows. MERGE=1: A row = (sum of 4 partials) * invS(head).
// ---------------------------------------------------------------------------
template<int MERGE>
__device__ __forceinline__ void gemm32(const float* __restrict__ A,
                                       const float* __restrict__ W,
                                       const float* __restrict__ bias,
                                       float* __restrict__ O)
{
    __shared__ __align__(16) float sA[2][16][36];
    __shared__ __align__(16) float sW[2][16][68];
    const int tid = threadIdx.x;
    const int r0 = blockIdx.x * 32, c0 = blockIdx.y * 64;
    const int ty = tid >> 4, tx = tid & 15;

    float acc[4][4];
#pragma unroll
    for (int i = 0; i < 4; ++i)
#pragma unroll
        for (int j = 0; j < 4; ++j) acc[i][j] = 0.f;

    const int arow = tid >> 2, ako = (tid & 3) << 2;
    const int wrow = tid >> 1, wko = (tid & 1) << 3;

    const float* ap = A + (r0 + arow) * DM + ako;
    const float* wp = W + (c0 + wrow) * DM + wko;

    float invS[HH];
    if (MERGE) {
        const float* sp = g_SP + (r0 + arow) * HH;
#pragma unroll
        for (int hh = 0; hh < HH; ++hh) {
            float s = sp[hh] + sp[BB*NN*HH + hh] + sp[2*BB*NN*HH + hh] + sp[3*BB*NN*HH + hh];
            invS[hh] = 1.0f / s;
        }
    }

    auto loadA = [&](int k0) -> float4 {
        if (MERGE) {
            float4 a0 = *(const float4*)(ap + k0);
            float4 a1 = *(const float4*)(ap + BB*NN*DM + k0);
            float4 a2 = *(const float4*)(ap + 2*BB*NN*DM + k0);
            float4 a3 = *(const float4*)(ap + 3*BB*NN*DM + k0);
            float is = invS[(k0 + ako) >> 5];
            return make_float4((a0.x+a1.x+a2.x+a3.x)*is, (a0.y+a1.y+a2.y+a3.y)*is,
                               (a0.z+a1.z+a2.z+a3.z)*is, (a0.w+a1.w+a2.w+a3.w)*is);
        }
        return *(const float4*)(ap + k0);
    };

    {
        float4 pa  = loadA(0);
        float4 pw0 = *(const float4*)(wp);
        float4 pw1 = *(const float4*)(wp + 4);
        sA[0][ako+0][arow] = pa.x; sA[0][ako+1][arow] = pa.y;
        sA[0][ako+2][arow] = pa.z; sA[0][ako+3][arow] = pa.w;
        sW[0][wko+0][wrow] = pw0.x; sW[0][wko+1][wrow] = pw0.y;
        sW[0][wko+2][wrow] = pw0.z; sW[0][wko+3][wrow] = pw0.w;
        sW[0][wko+4][wrow] = pw1.x; sW[0][wko+5][wrow] = pw1.y;
        sW[0][wko+6][wrow] = pw1.z; sW[0][wko+7][wrow] = pw1.w;
    }
    __syncthreads();

    int buf = 0;
    for (int k0 = 0; k0 < DM; k0 += 16, buf ^= 1) {
        const bool has_next = (k0 + 16 < DM);
        float4 pa, pw0, pw1;
        if (has_next) {
            pa  = loadA(k0 + 16);
            pw0 = *(const float4*)(wp + k0 + 16);
            pw1 = *(const float4*)(wp + k0 + 20);
        }
#pragma unroll
        for (int k = 0; k < 16; ++k) {
            float4 av = *(const float4*)&sA[buf][k][ty*4];
            float4 wv = *(const float4*)&sW[buf][k][tx*4];
            acc[0][0] = fmaf(av.x, wv.x, acc[0][0]);
            acc[0][1] = fmaf(av.x, wv.y, acc[0][1]);
            acc[0][2] = fmaf(av.x, wv.z, acc[0][2]);
            acc[0][3] = fmaf(av.x, wv.w, acc[0][3]);
            acc[1][0] = fmaf(av.y, wv.x, acc[1][0]);
            acc[1][1] = fmaf(av.y, wv.y, acc[1][1]);
            acc[1][2] = fmaf(av.y, wv.z, acc[1][2]);
            acc[1][3] = fmaf(av.y, wv.w, acc[1][3]);
            acc[2][0] = fmaf(av.z, wv.x, acc[2][0]);
            acc[2][1] = fmaf(av.z, wv.y, acc[2][1]);
            acc[2][2] = fmaf(av.z, wv.z, acc[2][2]);
            acc[2][3] = fmaf(av.z, wv.w, acc[2][3]);
            acc[3][0] = fmaf(av.w, wv.x, acc[3][0]);
            acc[3][1] = fmaf(av.w, wv.y, acc[3][1]);
            acc[3][2] = fmaf(av.w, wv.z, acc[3][2]);
            acc[3][3] = fmaf(av.w, wv.w, acc[3][3]);
        }
        if (has_next) {
            int nb = buf ^ 1;
            sA[nb][ako+0][arow] = pa.x; sA[nb][ako+1][arow] = pa.y;
            sA[nb][ako+2][arow] = pa.z; sA[nb][ako+3][arow] = pa.w;
            sW[nb][wko+0][wrow] = pw0.x; sW[nb][wko+1][wrow] = pw0.y;
            sW[nb][wko+2][wrow] = pw0.z; sW[nb][wko+3][wrow] = pw0.w;
            sW[nb][wko+4][wrow] = pw1.x; sW[nb][wko+5][wrow] = pw1.y;
            sW[nb][wko+6][wrow] = pw1.z; sW[nb][wko+7][wrow] = pw1.w;
        }
        __syncthreads();
    }
    float4 bv = *(const float4*)(bias + c0 + tx*4);
#pragma unroll
    for (int i = 0; i < 4; ++i) {
        float4 o = make_float4(acc[i][0]+bv.x, acc[i][1]+bv.y,
                               acc[i][2]+bv.z, acc[i][3]+bv.w);
        *(float4*)(O + (r0 + ty*4 + i) * DM + c0 + tx*4) = o;
    }
}

__global__ void __launch_bounds__(128) k_qkv(const float* __restrict__ h,
                                             const float* __restrict__ Wq,
                                             const float* __restrict__ Wk,
                                             const float* __restrict__ Wv,
                                             const float* __restrict__ bq,
                                             const float* __restrict__ bk,
                                             const float* __restrict__ bv)
{
    const int z = blockIdx.z;
    const float* W = (z == 0) ? Wq : (z == 1) ? Wk : Wv;
    const float* b = (z == 0) ? bq : (z == 1) ? bk : bv;
    float* O = (z == 0) ? g_Q : (z == 1) ? g_K : g_V;
    gemm32<0>(h, W, b, O);
}

__global__ void __launch_bounds__(128) k_out(const float* __restrict__ Wo,
                                             const float* __restrict__ bo,
                                             float* __restrict__ out)
{
    gemm32<1>(g_accP, Wo, bo, out);
}

// ---------------------------------------------------------------------------
// Fused attention, m-split x4, TQ=8, MT=32.
// grid: (NN/TQ, BB, MSPL) = (64, 2, 4) = 512 blocks, 256 threads, ~54KB smem,
// (256,3) -> 3 blocks/SM, ~24 warps/SM. No duplicated per-pair work.
// Partials (acc, Ssum) written to g_accP/g_SP; merged in k_out.
// ---------------------------------------------------------------------------
__global__ void __launch_bounds__(256, 3) k_attn(const float* __restrict__ X,
                                                 const float* __restrict__ EB,
                                                 const float* __restrict__ WKER,
                                                 const float* __restrict__ BETA)
{
    extern __shared__ __align__(16) float smem[];
    float* sK    = smem;                 // 32*260
    float* sQ    = sK + MT*KP;           // 8*256
    float* sS    = sQ + TQ*DM;           // 8q*8h*32m
    float* sXm   = sS + TQ*HH*MT;        // 32*25
    float* sXq   = sXm + MT*XP;          // 8*25 (odd pitch)
    float* sOne  = sXq + TQ*XP;          // 8
    float* sCoef = sOne + 8;             // 8*4

    const int b   = blockIdx.y;
    const int ms  = blockIdx.z;
    const int n0  = blockIdx.x * TQ;
    const int tid = threadIdx.x;

    const int qA = tid >> 5, mlA = tid & 31;   // phase A: warp = q row
    const int hB = tid >> 5, dB  = tid & 31;   // phase B: warp = head

    const float* kgb = g_K + (b*NN + ms*MR)*DM;
    const float* xgb = X + (b*NN + ms*MR)*24;

    int krow[8], kcol[8];
#pragma unroll
    for (int i = 0; i < 8; ++i) { int idx = tid + 256*i; krow[i] = idx >> 6; kcol[i] = idx & 63; }

    // ---- block setup ----
    {   // sQ: 8 rows x 256 floats = 512 float4, 256 threads x 2
#pragma unroll
        for (int i = 0; i < 2; ++i) {
            int idx = tid + 256*i;
            int q = idx >> 6, c4 = idx & 63;
            ((float4*)(sQ + q*DM))[c4] = ((const float4*)(g_Q + (b*NN + n0 + q)*DM))[c4];
        }
    }
    if (tid < TQ*24) {
        int q = tid / 24, j = tid - q*24;
        sXq[q*XP + j] = X[(b*NN + n0 + q)*24 + j];
    }
    if (tid < HH*3) {
        int hh = tid/3, c = tid%3;
        float w = WKER[hh*3+c] * BETA[hh] * LOG2E;
        sCoef[hh*4+c] = (c == 1) ? w : -w;   // [-dh, +sdot, -de2]
    }
    {   // stage X tile 0: 32 rows x 24 = 768 floats = 256 x 3
#pragma unroll
        for (int i = 0; i < 3; ++i) {
            int idx = tid + 256*i;
            int row = idx / 24, c = idx - row*24;
            sXm[row*XP + c] = xgb[idx];
        }
    }
    {   // stage K tile 0 via cp.async: 32 rows x 64 float4 = 2048 chunks
#pragma unroll
        for (int i = 0; i < 8; ++i)
            cpa16(&sK[krow[i]*KP + kcol[i]*4], kgb + krow[i]*DM + kcol[i]*4);
        cpa_commit();
    }
    __syncthreads();
    if (tid < TQ) {
        float s = 0.f;
#pragma unroll
        for (int j = 0; j < 8; ++j) s = fmaf(sXq[tid*XP+j], sXq[tid*XP+j], s);
        sOne[tid] = 1.0f - s;
    }

    float Ssum[TQ], acc[TQ];
#pragma unroll
    for (int q = 0; q < TQ; ++q) { Ssum[q] = 0.f; acc[q] = 0.f; }

    cpa_wait0();
    __syncthreads();

    for (int t = 0; t < NT; ++t) {
        // ---- Phase A: geometry + RoPE scores -> p = 2^sc ----
        {
            const float* xm  = &sXm[mlA*XP];
            const float* xqp = &sXq[qA*XP];        // warp-broadcast reads
            float dh2 = 0.f, om = 1.0f, sd = 0.f, de2 = 0.f;
#pragma unroll
            for (int j = 0; j < 8; ++j) {
                float c = xm[j];
                float d = xqp[j] - c;
                dh2 = fmaf(d, d, dh2);
                om  = fmaf(-c, c, om);
            }
#pragma unroll
            for (int j = 0; j < 8; ++j) sd = fmaf(xqp[8+j], xm[8+j], sd);
#pragma unroll
            for (int j = 0; j < 8; ++j) {
                float d = xqp[16+j] - xm[16+j];
                de2 = fmaf(d, d, de2);
            }
            float tt = fmaxf(2.0f * dh2 / (sOne[qA] * om), 1e-6f);
            float dh = __logf(1.0f + tt + sqrtf(tt * (tt + 2.0f)));
            float sdc = fminf(fmaxf(sd, -1.0f + 1e-6f), 1.0f - 1e-6f);
            float ds = acosf(sdc);
            float dist = sqrtf(fmaf(dh, dh, fmaf(ds, ds, de2)));

            float cs[HF], sn[HF];
#pragma unroll
            for (int f = 0; f < HF; ++f) __sincosf(dist * cFREQ[f], &sn[f], &cs[f]);

            const float ebl = EB[(b*NN + n0 + qA)*NN + ms*MR + t*MT + mlA] * LOG2E;
            const float* krowp = &sK[mlA*KP];

#pragma unroll
            for (int hh = 0; hh < HH; ++hh) {
                const float4* kq = (const float4*)(krowp + hh*HD);
                const float4* qq = (const float4*)(sQ + qA*DM + hh*HD);
                float sa = 0.f, sb = 0.f;
#pragma unroll
                for (int f4 = 0; f4 < 8; ++f4) {
                    float4 kv = kq[f4];
                    float4 qv = qq[f4];
                    const int f0 = f4*2;
                    float same0 = fmaf(qv.x, kv.x, qv.y*kv.y);
                    float crs0  = fmaf(qv.x, kv.y, -qv.y*kv.x);
                    sa = fmaf(cs[f0], same0, sa);
                    sb = fmaf(sn[f0], crs0,  sb);
                    float same1 = fmaf(qv.z, kv.z, qv.w*kv.w);
                    float crs1  = fmaf(qv.z, kv.w, -qv.w*kv.z);
                    sa = fmaf(cs[f0+1], same1, sa);
                    sb = fmaf(sn[f0+1], crs1,  sb);
                }
                float sc = fmaf(sa + sb, SCALE * LOG2E, ebl);
                sc = fmaf(sCoef[hh*4+0], dh,  sc);
                sc = fmaf(sCoef[hh*4+1], sd,  sc);
                sc = fmaf(sCoef[hh*4+2], de2, sc);
                sS[(qA*HH + hh)*MT + mlA] = ex2(sc);
            }
        }
        __syncthreads();   // sS(p) ready; sK/sXm free for restage

        // ---- restage next tile (overlaps phase B) ----
        if (t + 1 < NT) {
            const float* kg = kgb + (t+1)*MT*DM;
#pragma unroll
            for (int i = 0; i < 8; ++i)
                cpa16(&sK[krow[i]*KP + kcol[i]*4], kg + krow[i]*DM + kcol[i]*4);
            cpa_commit();
            const float* xg = xgb + (t+1)*MT*24;
#pragma unroll
            for (int i = 0; i < 3; ++i) {
                int idx = tid + 256*i;
                int row = idx / 24, c = idx - row*24;
                sXm[row*XP + c] = xg[idx];
            }
        }

        // ---- Phase B: normalizer sum + PV (thread = head,dim; q = 0..7) ----
        {
#pragma unroll
            for (int q = 0; q < TQ; ++q)
                Ssum[q] += sS[(q*HH + hB)*MT + dB];
            const float* vb = g_V + (b*NN + ms*MR + t*MT)*DM + hB*HD + dB;
#pragma unroll 4
            for (int m4 = 0; m4 < MT/4; ++m4) {
                float v0 = vb[(m4*4+0)*DM];
                float v1 = vb[(m4*4+1)*DM];
                float v2 = vb[(m4*4+2)*DM];
                float v3 = vb[(m4*4+3)*DM];
#pragma unroll
                for (int q = 0; q < TQ; ++q) {
                    float4 p = *(const float4*)&sS[(q*HH + hB)*MT + m4*4];
                    acc[q] = fmaf(p.x, v0, fmaf(p.y, v1, fmaf(p.z, v2, fmaf(p.w, v3, acc[q]))));
                }
            }
        }
        cpa_wait0();
        __syncthreads();
    }

    // ---- write partials ----
    float* accp = g_accP + ms*(BB*NN*DM);
    float* sp   = g_SP   + ms*(BB*NN*HH);
#pragma unroll
    for (int q = 0; q < TQ; ++q) {
        float s = Ssum[q];
#pragma unroll
        for (int o = 16; o; o >>= 1) s += __shfl_xor_sync(0xffffffffu, s, o);
        accp[(b*NN + n0 + q)*DM + hB*HD + dB] = acc[q];
        if (dB == 0) sp[(b*NN + n0 + q)*HH + hB] = s;
    }
}

// ---------------------------------------------------------------------------
extern "C" void kernel_launch(void* const* d_in, const int* in_sizes, int n_in,
                              void* d_out, int out_size)
{
    (void)in_sizes; (void)n_in; (void)out_size;
    const float* h    = (const float*)d_in[0];
    const float* x    = (const float*)d_in[1];
    const float* Wq   = (const float*)d_in[2];
    const float* bq   = (const float*)d_in[3];
    const float* Wk   = (const float*)d_in[4];
    const float* bk   = (const float*)d_in[5];
    const float* Wv   = (const float*)d_in[6];
    const float* bv   = (const float*)d_in[7];
    const float* Wo   = (const float*)d_in[8];
    const float* bo   = (const float*)d_in[9];
    const float* wker = (const float*)d_in[10];
    const float* beta = (const float*)d_in[11];
    const float* eb   = (const float*)d_in[12];
    float* out = (float*)d_out;

    const int smem_attn = (MT*KP + TQ*DM + TQ*HH*MT + MT*XP + TQ*XP + 8 + HH*4)
                          * (int)sizeof(float);
    static int attr_set = 0;
    if (!attr_set) {
        cudaFuncSetAttribute(k_attn, cudaFuncAttributeMaxDynamicSharedMemorySize, smem_attn);
        attr_set = 1;
    }

    k_qkv<<<dim3((BB*NN)/32, DM/64, 3), 128>>>(h, Wq, Wk, Wv, bq, bk, bv);
    k_attn<<<dim3(NN/TQ, BB, MSPL), 256, smem_attn>>>(x, eb, wker, beta);
    k_out<<<dim3((BB*NN)/32, DM/64), 128>>>(Wo, bo, out);
}

// round 16
// speedup vs baseline: 1.0873x; 1.0194x over previous
#include <cuda_runtime.h>

#define BB 2
#define NN 512
#define DM 256
#define HH 8
#define HD 32
#define HF 16
#define TQ 4          // query rows per block
#define MT 64         // key rows per tile
#define NT (NN/MT)    // 8 tiles
#define KP 260        // sK row pitch
#define XP 25         // sXm row pitch
#define SCALE 0.17677669529663687f
#define LOG2E 1.4426950408889634f

__device__ float g_Q[BB*NN*DM];
__device__ float g_K[BB*NN*DM];
__device__ float g_V[BB*NN*DM];
__device__ float g_ctx[BB*NN*DM];

__constant__ float cFREQ[HF] = {
    1.0f, 0.5623413251903491f, 0.31622776601683794f, 0.17782794100389228f,
    0.1f, 0.05623413251903491f, 0.031622776601683794f, 0.017782794100389228f,
    0.01f, 0.005623413251903491f, 0.0031622776601683794f, 0.0017782794100389228f,
    0.001f, 0.0005623413251903491f, 0.00031622776601683794f, 0.00017782794100389228f };

__device__ __forceinline__ float ex2(float x) {
    float r; asm("ex2.approx.ftz.f32 %0, %1;" : "=f"(r) : "f"(x)); return r;
}

// ---- cp.async helpers -------------------------------------------------------
__device__ __forceinline__ void cpa16(void* smem_ptr, const void* gptr) {
    unsigned sa = (unsigned)__cvta_generic_to_shared(smem_ptr);
    asm volatile("cp.async.cg.shared.global [%0], [%1], 16;\n" :: "r"(sa), "l"(gptr) : "memory");
}
__device__ __forceinline__ void cpa_commit() {
    asm volatile("cp.async.commit_group;\n" ::: "memory");
}
__device__ __forceinline__ void cpa_wait0() {
    asm volatile("cp.async.wait_group 0;\n" ::: "memory");
}

// ---------------------------------------------------------------------------
// k-major staged GEMM, double-buffered smem. [R6-verified]
// block = 128 threads, tile 32 rows x 64 cols, thread tile 4x4.
// ---------------------------------------------------------------------------
__device__ __forceinline__ void gemm32(const float* __restrict__ A,
                                       const float* __restrict__ W,
                                       const float* __restrict__ bias,
                                       float* __restrict__ O)
{
    __shared__ __align__(16) float sA[2][16][36];
    __shared__ __align__(16) float sW[2][16][68];
    const int tid = threadIdx.x;
    const int r0 = blockIdx.x * 32, c0 = blockIdx.y * 64;
    const int ty = tid >> 4, tx = tid & 15;

    float acc[4][4];
#pragma unroll
    for (int i = 0; i < 4; ++i)
#pragma unroll
        for (int j = 0; j < 4; ++j) acc[i][j] = 0.f;

    const int arow = tid >> 2, ako = (tid & 3) << 2;
    const int wrow = tid >> 1, wko = (tid & 1) << 3;

    const float* ap = A + (r0 + arow) * DM + ako;
    const float* wp = W + (c0 + wrow) * DM + wko;

    {
        float4 pa  = *(const float4*)(ap);
        float4 pw0 = *(const float4*)(wp);
        float4 pw1 = *(const float4*)(wp + 4);
        sA[0][ako+0][arow] = pa.x; sA[0][ako+1][arow] = pa.y;
        sA[0][ako+2][arow] = pa.z; sA[0][ako+3][arow] = pa.w;
        sW[0][wko+0][wrow] = pw0.x; sW[0][wko+1][wrow] = pw0.y;
        sW[0][wko+2][wrow] = pw0.z; sW[0][wko+3][wrow] = pw0.w;
        sW[0][wko+4][wrow] = pw1.x; sW[0][wko+5][wrow] = pw1.y;
        sW[0][wko+6][wrow] = pw1.z; sW[0][wko+7][wrow] = pw1.w;
    }
    __syncthreads();

    int buf = 0;
    for (int k0 = 0; k0 < DM; k0 += 16, buf ^= 1) {
        const bool has_next = (k0 + 16 < DM);
        float4 pa, pw0, pw1;
        if (has_next) {
            pa  = *(const float4*)(ap + k0 + 16);
            pw0 = *(const float4*)(wp + k0 + 16);
            pw1 = *(const float4*)(wp + k0 + 20);
        }
#pragma unroll
        for (int k = 0; k < 16; ++k) {
            float4 av = *(const float4*)&sA[buf][k][ty*4];
            float4 wv = *(const float4*)&sW[buf][k][tx*4];
            acc[0][0] = fmaf(av.x, wv.x, acc[0][0]);
            acc[0][1] = fmaf(av.x, wv.y, acc[0][1]);
            acc[0][2] = fmaf(av.x, wv.z, acc[0][2]);
            acc[0][3] = fmaf(av.x, wv.w, acc[0][3]);
            acc[1][0] = fmaf(av.y, wv.x, acc[1][0]);
            acc[1][1] = fmaf(av.y, wv.y, acc[1][1]);
            acc[1][2] = fmaf(av.y, wv.z, acc[1][2]);
            acc[1][3] = fmaf(av.y, wv.w, acc[1][3]);
            acc[2][0] = fmaf(av.z, wv.x, acc[2][0]);
            acc[2][1] = fmaf(av.z, wv.y, acc[2][1]);
            acc[2][2] = fmaf(av.z, wv.z, acc[2][2]);
            acc[2][3] = fmaf(av.z, wv.w, acc[2][3]);
            acc[3][0] = fmaf(av.w, wv.x, acc[3][0]);
            acc[3][1] = fmaf(av.w, wv.y, acc[3][1]);
            acc[3][2] = fmaf(av.w, wv.z, acc[3][2]);
            acc[3][3] = fmaf(av.w, wv.w, acc[3][3]);
        }
        if (has_next) {
            int nb = buf ^ 1;
            sA[nb][ako+0][arow] = pa.x; sA[nb][ako+1][arow] = pa.y;
            sA[nb][ako+2][arow] = pa.z; sA[nb][ako+3][arow] = pa.w;
            sW[nb][wko+0][wrow] = pw0.x; sW[nb][wko+1][wrow] = pw0.y;
            sW[nb][wko+2][wrow] = pw0.z; sW[nb][wko+3][wrow] = pw0.w;
            sW[nb][wko+4][wrow] = pw1.x; sW[nb][wko+5][wrow] = pw1.y;
            sW[nb][wko+6][wrow] = pw1.z; sW[nb][wko+7][wrow] = pw1.w;
        }
        __syncthreads();
    }
    float4 bv = *(const float4*)(bias + c0 + tx*4);
#pragma unroll
    for (int i = 0; i < 4; ++i) {
        float4 o = make_float4(acc[i][0]+bv.x, acc[i][1]+bv.y,
                               acc[i][2]+bv.z, acc[i][3]+bv.w);
        *(float4*)(O + (r0 + ty*4 + i) * DM + c0 + tx*4) = o;
    }
}

__global__ void __launch_bounds__(128) k_qkv(const float* __restrict__ h,
                                             const float* __restrict__ Wq,
                                             const float* __restrict__ Wk,
                                             const float* __restrict__ Wv,
                                             const float* __restrict__ bq,
                                             const float* __restrict__ bk,
                                             const float* __restrict__ bv)
{
    const int z = blockIdx.z;
    const float* W = (z == 0) ? Wq : (z == 1) ? Wk : Wv;
    const float* b = (z == 0) ? bq : (z == 1) ? bk : bv;
    float* O = (z == 0) ? g_Q : (z == 1) ? g_K : g_V;
    gemm32(h, W, b, O);
}

__global__ void __launch_bounds__(128) k_out(const float* __restrict__ Wo,
                                             const float* __restrict__ bo,
                                             float* __restrict__ out)
{
    gemm32(g_ctx, Wo, bo, out);
}

// ---------------------------------------------------------------------------
// Fused attention (R13 champion) with PV unroll 8 for V-load MLP.
// grid: (NN/TQ, BB) = (128, 2), block: 256 threads
// ---------------------------------------------------------------------------
__global__ void __launch_bounds__(256, 2) k_attn(const float* __restrict__ X,
                                                 const float* __restrict__ EB,
                                                 const float* __restrict__ WKER,
                                                 const float* __restrict__ BETA)
{
    extern __shared__ __align__(16) float smem[];
    float* sK    = smem;                 // 64*260
    float* sQ    = sK + MT*KP;           // 4*256
    float* sS    = sQ + TQ*DM;           // 4*8*64
    float* sXm   = sS + TQ*HH*MT;        // 64*25
    float* sCoef = sXm + MT*XP;          // 8*4

    const int b   = blockIdx.y;
    const int n0  = blockIdx.x * TQ;
    const int tid = threadIdx.x;

    const int qA = tid >> 6, mlA = tid & 63;   // phase A identity
    const int hB = tid >> 5, dB  = tid & 31;   // phase B identity

    const float* kgb = g_K + b*NN*DM;
    const float* xgb = X + b*NN*24;

    int krow[16], kcol[16];
#pragma unroll
    for (int i = 0; i < 16; ++i) { int idx = tid + 256*i; krow[i] = idx >> 6; kcol[i] = idx & 63; }

    // ---- block setup ----
    {
        int q = tid >> 6, i = tid & 63;
        ((float4*)sQ)[tid] = ((const float4*)(g_Q + (b*NN + n0 + q)*DM))[i];
    }
    if (tid < HH*3) {
        int hh = tid/3, c = tid%3;
        float w = WKER[hh*3+c] * BETA[hh] * LOG2E;   // fold log2e
        sCoef[hh*4+c] = (c == 1) ? w : -w;           // [-dh, +sdot, -de2]
    }
    {
        const float* xg = xgb;
#pragma unroll
        for (int i = 0; i < 6; ++i) {
            int idx = tid + 256*i;
            int row = idx / 24, c = idx - row*24;
            sXm[row*XP + c] = xg[idx];
        }
    }
    {
        const float* kg = kgb;
#pragma unroll
        for (int i = 0; i < 16; ++i)
            cpa16(&sK[krow[i]*KP + kcol[i]*4], kg + krow[i]*DM + kcol[i]*4);
        cpa_commit();
    }

    float xq[24];
    {
        const float* xp = X + (b*NN + n0 + qA)*24;
#pragma unroll
        for (int j = 0; j < 24; ++j) xq[j] = xp[j];
    }
    float oneq = 1.0f;
#pragma unroll
    for (int j = 0; j < 8; ++j) oneq = fmaf(-xq[j], xq[j], oneq);

    float Ssum[TQ], acc[TQ];
#pragma unroll
    for (int q = 0; q < TQ; ++q) { Ssum[q] = 0.f; acc[q] = 0.f; }

    cpa_wait0();
    __syncthreads();

    for (int t = 0; t < NT; ++t) {
        // ---- Phase A: geometry + RoPE scores -> p = 2^sc ----
        {
            const float* xm = &sXm[mlA*XP];
            float dh2 = 0.f, om = 1.0f, sd = 0.f, de2 = 0.f;
#pragma unroll
            for (int j = 0; j < 8; ++j) {
                float c = xm[j];
                float d = xq[j] - c;
                dh2 = fmaf(d, d, dh2);
                om  = fmaf(-c, c, om);
            }
#pragma unroll
            for (int j = 0; j < 8; ++j) sd = fmaf(xq[8+j], xm[8+j], sd);
#pragma unroll
            for (int j = 0; j < 8; ++j) {
                float d = xq[16+j] - xm[16+j];
                de2 = fmaf(d, d, de2);
            }
            float tt = fmaxf(2.0f * dh2 / (oneq * om), 1e-6f);
            float dh = __logf(1.0f + tt + sqrtf(tt * (tt + 2.0f)));
            float sdc = fminf(fmaxf(sd, -1.0f + 1e-6f), 1.0f - 1e-6f);
            float ds = acosf(sdc);
            float dist = sqrtf(fmaf(dh, dh, fmaf(ds, ds, de2)));

            float cs[HF], sn[HF];
#pragma unroll
            for (int f = 0; f < HF; ++f) __sincosf(dist * cFREQ[f], &sn[f], &cs[f]);

            const float ebl = EB[(b*NN + n0 + qA)*NN + t*MT + mlA] * LOG2E;
            const float* krowp = &sK[mlA*KP];

#pragma unroll
            for (int hh = 0; hh < HH; ++hh) {
                const float4* kq = (const float4*)(krowp + hh*HD);
                const float4* qq = (const float4*)(sQ + qA*DM + hh*HD);
                float sa = 0.f, sb = 0.f;
#pragma unroll
                for (int f4 = 0; f4 < 8; ++f4) {
                    float4 kv = kq[f4];
                    float4 qv = qq[f4];
                    const int f0 = f4*2;
                    float same0 = fmaf(qv.x, kv.x, qv.y*kv.y);
                    float crs0  = fmaf(qv.x, kv.y, -qv.y*kv.x);
                    sa = fmaf(cs[f0], same0, sa);
                    sb = fmaf(sn[f0], crs0,  sb);
                    float same1 = fmaf(qv.z, kv.z, qv.w*kv.w);
                    float crs1  = fmaf(qv.z, kv.w, -qv.w*kv.z);
                    sa = fmaf(cs[f0+1], same1, sa);
                    sb = fmaf(sn[f0+1], crs1,  sb);
                }
                float sc = fmaf(sa + sb, SCALE * LOG2E, ebl);
                sc = fmaf(sCoef[hh*4+0], dh,  sc);
                sc = fmaf(sCoef[hh*4+1], sd,  sc);
                sc = fmaf(sCoef[hh*4+2], de2, sc);
                sS[(qA*HH + hh)*MT + mlA] = ex2(sc);
            }
        }
        __syncthreads();   // sS(p) ready; sK/sXm free for restage

        // ---- restage next tile (overlaps phase B) ----
        if (t + 1 < NT) {
            const float* kg = kgb + (t+1)*MT*DM;
#pragma unroll
            for (int i = 0; i < 16; ++i)
                cpa16(&sK[krow[i]*KP + kcol[i]*4], kg + krow[i]*DM + kcol[i]*4);
            cpa_commit();
            const float* xg = xgb + (t+1)*MT*24;
#pragma unroll
            for (int i = 0; i < 6; ++i) {
                int idx = tid + 256*i;
                int row = idx / 24, c = idx - row*24;
                sXm[row*XP + c] = xg[idx];
            }
        }

        // ---- Phase B: normalizer sum (read-only) + PV (unroll 8 for MLP) ----
        {
#pragma unroll
            for (int q = 0; q < TQ; ++q) {
                const float* srow = &sS[(q*HH + hB)*MT];
                Ssum[q] += srow[dB] + srow[dB + 32];
            }
            const float* vb = g_V + (b*NN + t*MT)*DM + hB*HD + dB;
#pragma unroll
            for (int m8 = 0; m8 < MT/8; ++m8) {
                float v0 = vb[(m8*8+0)*DM];
                float v1 = vb[(m8*8+1)*DM];
                float v2 = vb[(m8*8+2)*DM];
                float v3 = vb[(m8*8+3)*DM];
                float v4 = vb[(m8*8+4)*DM];
                float v5 = vb[(m8*8+5)*DM];
                float v6 = vb[(m8*8+6)*DM];
                float v7 = vb[(m8*8+7)*DM];
#pragma unroll
                for (int q = 0; q < TQ; ++q) {
                    const float* srow = &sS[(q*HH + hB)*MT + m8*8];
                    float4 p0 = *(const float4*)(srow);
                    float4 p1 = *(const float4*)(srow + 4);
                    float a = acc[q];
                    a = fmaf(p0.x, v0, a);
                    a = fmaf(p0.y, v1, a);
                    a = fmaf(p0.z, v2, a);
                    a = fmaf(p0.w, v3, a);
                    a = fmaf(p1.x, v4, a);
                    a = fmaf(p1.y, v5, a);
                    a = fmaf(p1.z, v6, a);
                    a = fmaf(p1.w, v7, a);
                    acc[q] = a;
                }
            }
        }
        cpa_wait0();
        __syncthreads();
    }

    // ---- final: reduce normalizer once, write out ----
#pragma unroll
    for (int q = 0; q < TQ; ++q) {
        float s = Ssum[q];
#pragma unroll
        for (int o = 16; o; o >>= 1) s += __shfl_xor_sync(0xffffffffu, s, o);
        g_ctx[(b*NN + n0 + q)*DM + tid] = acc[q] * (1.0f / s);
    }
}

// ---------------------------------------------------------------------------
extern "C" void kernel_launch(void* const* d_in, const int* in_sizes, int n_in,
                              void* d_out, int out_size)
{
    (void)in_sizes; (void)n_in; (void)out_size;
    const float* h    = (const float*)d_in[0];
    const float* x    = (const float*)d_in[1];
    const float* Wq   = (const float*)d_in[2];
    const float* bq   = (const float*)d_in[3];
    const float* Wk   = (const float*)d_in[4];
    const float* bk   = (const float*)d_in[5];
    const float* Wv   = (const float*)d_in[6];
    const float* bv   = (const float*)d_in[7];
    const float* Wo   = (const float*)d_in[8];
    const float* bo   = (const float*)d_in[9];
    const float* wker = (const float*)d_in[10];
    const float* beta = (const float*)d_in[11];
    const float* eb   = (const float*)d_in[12];
    float* out = (float*)d_out;

    const int smem_attn = (MT*KP + TQ*DM + TQ*HH*MT + MT*XP + HH*4) * (int)sizeof(float);
    static int attr_set = 0;
    if (!attr_set) {
        cudaFuncSetAttribute(k_attn, cudaFuncAttributeMaxDynamicSharedMemorySize, smem_attn);
        attr_set = 1;
    }

    k_qkv<<<dim3((BB*NN)/32, DM/64, 3), 128>>>(h, Wq, Wk, Wv, bq, bk, bv);
    k_attn<<<dim3(NN/TQ, BB), 256, smem_attn>>>(x, eb, wker, beta);
    k_out<<<dim3((BB*NN)/32, DM/64), 128>>>(Wo, bo, out);
}